// round 14
// baseline (speedup 1.0000x reference)
#include <cuda_runtime.h>
#include <cuda_fp16.h>
#include <cstdint>

#define B_ROWS   8192
#define F_DIM    512
#define N_INT    1023
#define N_PAD    1024
#define N_LEAVES 1024
#define LEAF_D   64
#define DEPTH    10

// Scratch (allocation-free device globals)
__device__ float  g_P[B_ROWS * N_PAD];      // sigmoid(xW+b), col 1023 junk
__device__ __half g_Xh[B_ROWS * F_DIM];     // x in fp16
__device__ __half g_Wh[N_PAD * F_DIM];      // W^T in fp16: [n][k], row 1023 zero
__device__ uint2  g_Lfrag[8 * 64 * 32];     // leaves in HMMA B-fragment order

__device__ __forceinline__ uint32_t smem_u32(const void* p) {
    uint32_t a;
    asm("{ .reg .u64 t; cvta.to.shared.u64 t, %1; cvt.u32.u64 %0, t; }" : "=r"(a) : "l"(p));
    return a;
}

// m16n8k16 fp16 MMA, f32 accum
__device__ __forceinline__ void mma_f16(float* d, const uint32_t* a,
                                        uint32_t b0, uint32_t b1) {
    asm volatile(
        "mma.sync.aligned.m16n8k16.row.col.f32.f16.f16.f32 "
        "{%0,%1,%2,%3}, {%4,%5,%6,%7}, {%8,%9}, {%0,%1,%2,%3};"
        : "+f"(d[0]), "+f"(d[1]), "+f"(d[2]), "+f"(d[3])
        : "r"(a[0]), "r"(a[1]), "r"(a[2]), "r"(a[3]), "r"(b0), "r"(b1));
}

#define LDSM_X4(r0, r1, r2, r3, addr)                                          \
    asm volatile("ldmatrix.sync.aligned.m8n8.x4.shared.b16 {%0,%1,%2,%3}, [%4];" \
                 : "=r"(r0), "=r"(r1), "=r"(r2), "=r"(r3) : "r"(addr))

#define CP_ASYNC16(saddr, gptr)                                                \
    asm volatile("cp.async.cg.shared.global [%0], [%1], 16;"                   \
                 :: "r"(saddr), "l"(gptr) : "memory")
#define CP_COMMIT()  asm volatile("cp.async.commit_group;" ::: "memory")
#define CP_WAIT1()   asm volatile("cp.async.wait_group 1;" ::: "memory")

// ===========================================================================
// Converters (run once per launch)
// ===========================================================================
__global__ __launch_bounds__(256)
void convert_x_kernel(const float* __restrict__ x)
{
    const int i = (blockIdx.x * 256 + threadIdx.x) * 8;
    float4 v0 = *(const float4*)(x + i);
    float4 v1 = *(const float4*)(x + i + 4);
    __half2 h0 = __floats2half2_rn(v0.x, v0.y);
    __half2 h1 = __floats2half2_rn(v0.z, v0.w);
    __half2 h2 = __floats2half2_rn(v1.x, v1.y);
    __half2 h3 = __floats2half2_rn(v1.z, v1.w);
    uint4 u;
    u.x = *(uint32_t*)&h0; u.y = *(uint32_t*)&h1;
    u.z = *(uint32_t*)&h2; u.w = *(uint32_t*)&h3;
    *(uint4*)(g_Xh + i) = u;
}

__global__ void convert_w_kernel(const float* __restrict__ W)
{
    __shared__ float t[32][33];
    const int tx = threadIdx.x, ty = threadIdx.y;
    const int n0 = blockIdx.x * 32, k0 = blockIdx.y * 32;
    #pragma unroll
    for (int i = 0; i < 4; ++i) {
        int k = k0 + ty + i * 8;
        int n = n0 + tx;
        t[ty + i * 8][tx] = (n < N_INT) ? W[(size_t)k * N_INT + n] : 0.0f;
    }
    __syncthreads();
    #pragma unroll
    for (int i = 0; i < 4; ++i) {
        int n = n0 + ty + i * 8;
        g_Wh[(size_t)n * F_DIM + k0 + tx] = __float2half_rn(t[tx][ty + i * 8]);
    }
}

// leaves [1024][64] -> g_Lfrag: exact per-lane HMMA B fragments.
__global__ __launch_bounds__(256)
void convert_leaves_kernel(const float* __restrict__ leaves)
{
    const int tid  = blockIdx.x * 256 + threadIdx.x;   // 0..16383
    const int wid  = tid >> 11;
    const int kt   = (tid >> 5) & 63;
    const int lane = tid & 31;
    const int n  = wid * 8 + (lane >> 2);
    const int k0 = kt * 16 + (lane & 3) * 2;
    __half2 b0 = __floats2half2_rn(leaves[(size_t)k0 * LEAF_D + n],
                                   leaves[(size_t)(k0 + 1) * LEAF_D + n]);
    __half2 b1 = __floats2half2_rn(leaves[(size_t)(k0 + 8) * LEAF_D + n],
                                   leaves[(size_t)(k0 + 9) * LEAF_D + n]);
    uint2 u;
    u.x = *(uint32_t*)&b0;
    u.y = *(uint32_t*)&b1;
    g_Lfrag[tid] = u;
}

// ===========================================================================
// Kernel 1: P = sigmoid(x @ W + b). fp16 ldmatrix + mma, cp.async 3-stage.
// 256 threads = 8 warps (2M x 4N), warp tile 64x32, CTA 128x128, BK=64
// (8 barriers instead of 16; K=192 prefetch depth; 128B rows, SW128
// swizzle chunk ^= row&7). Accumulation order identical to BK=32 version.
// ===========================================================================
#define G1_TSTAGE 16384                    // one tensor, one stage: 128 x 128B
#define G1_SMEM   (6 * G1_TSTAGE)          // 3 stages x (A + B) = 96KB

__global__ __launch_bounds__(256, 2)
void gemm1_kernel(const float* __restrict__ bias)
{
    extern __shared__ char smem[];
    const uint32_t sbase = smem_u32(smem);
    const int tid  = threadIdx.x;
    const int lane = tid & 31;
    const int wid  = tid >> 5;
    const int wm   = (wid & 1) * 64;
    const int wn   = (wid >> 1) * 32;
    const int row0 = blockIdx.y * 128;
    const int col0 = blockIdx.x * 128;

    float acc[4][4][4];
    #pragma unroll
    for (int mt = 0; mt < 4; ++mt)
        #pragma unroll
        for (int nt = 0; nt < 4; ++nt)
            #pragma unroll
            for (int i = 0; i < 4; ++i) acc[mt][nt][i] = 0.0f;

    // ---- async loader: thread -> row lr, chunks cb..cb+3 (16B each) ----
    const int lr = tid >> 1;               // 0..127
    const int cb = (tid & 1) * 4;          // 0 or 4
    const int xr = lr & 7;
    const uint32_t so0 = (uint32_t)(lr * 128 + (((cb + 0) ^ xr) << 4));
    const uint32_t so1 = (uint32_t)(lr * 128 + (((cb + 1) ^ xr) << 4));
    const uint32_t so2 = (uint32_t)(lr * 128 + (((cb + 2) ^ xr) << 4));
    const uint32_t so3 = (uint32_t)(lr * 128 + (((cb + 3) ^ xr) << 4));
    const __half* gA = g_Xh + (size_t)(row0 + lr) * F_DIM + cb * 8;
    const __half* gB = g_Wh + (size_t)(col0 + lr) * F_DIM + cb * 8;

    #define LOAD_STAGE(st, bk)                                                 \
    do {                                                                       \
        uint32_t a_ = sbase + (st) * G1_TSTAGE;                                \
        uint32_t b_ = sbase + 3 * G1_TSTAGE + (st) * G1_TSTAGE;                \
        CP_ASYNC16(a_ + so0, gA + (bk));                                       \
        CP_ASYNC16(a_ + so1, gA + (bk) + 8);                                   \
        CP_ASYNC16(a_ + so2, gA + (bk) + 16);                                  \
        CP_ASYNC16(a_ + so3, gA + (bk) + 24);                                  \
        CP_ASYNC16(b_ + so0, gB + (bk));                                       \
        CP_ASYNC16(b_ + so1, gB + (bk) + 8);                                   \
        CP_ASYNC16(b_ + so2, gB + (bk) + 16);                                  \
        CP_ASYNC16(b_ + so3, gB + (bk) + 24);                                  \
    } while (0)

    // ---- ldmatrix per-lane bases ----
    const int arow = wm + (lane & 15);
    const int ax   = arow & 7;
    const int ahi  = lane >> 4;                    // 0/1
    const int brow = wn + (lane & 7) + ((lane >> 4) << 3);
    const int bx   = brow & 7;
    const int bhi  = (lane >> 3) & 1;

    #define COMPUTE(st)                                                        \
    do {                                                                       \
        const uint32_t ab = sbase + (st) * G1_TSTAGE;                          \
        const uint32_t bb = sbase + 3 * G1_TSTAGE + (st) * G1_TSTAGE;          \
        _Pragma("unroll")                                                      \
        for (int s = 0; s < 4; ++s) {                                          \
            const uint32_t aA = (uint32_t)(arow * 128 +                        \
                                 (((2 * s + ahi) ^ ax) << 4));                 \
            const uint32_t bA = (uint32_t)(brow * 128 +                        \
                                 (((2 * s + bhi) ^ bx) << 4));                 \
            uint32_t a[4][4], b[2][4];                                         \
            _Pragma("unroll")                                                  \
            for (int mt = 0; mt < 4; ++mt)                                     \
                LDSM_X4(a[mt][0], a[mt][1], a[mt][2], a[mt][3],                \
                        ab + aA + mt * 2048);                                  \
            _Pragma("unroll")                                                  \
            for (int n2 = 0; n2 < 2; ++n2)                                     \
                LDSM_X4(b[n2][0], b[n2][1], b[n2][2], b[n2][3],                \
                        bb + bA + n2 * 2048);                                  \
            _Pragma("unroll")                                                  \
            for (int mt = 0; mt < 4; ++mt)                                     \
                _Pragma("unroll")                                              \
                for (int nt = 0; nt < 4; ++nt)                                 \
                    mma_f16(acc[mt][nt], a[mt],                                \
                            b[nt >> 1][(nt & 1) * 2],                          \
                            b[nt >> 1][(nt & 1) * 2 + 1]);                     \
        }                                                                      \
    } while (0)

    LOAD_STAGE(0, 0);  CP_COMMIT();
    LOAD_STAGE(1, 64); CP_COMMIT();

    for (int it = 0; it < 8; ++it) {
        CP_WAIT1();
        __syncthreads();
        if (it < 6) LOAD_STAGE((it + 2) % 3, (it + 2) * 64);
        CP_COMMIT();
        COMPUTE(it % 3);
    }
    #undef COMPUTE
    #undef LOAD_STAGE

    // Epilogue: bias + sigmoid -> g_P
    const int g = lane >> 2, t = lane & 3;
    #pragma unroll
    for (int nt = 0; nt < 4; ++nt) {
        const int col = col0 + wn + nt * 8 + 2 * t;
        const float b0 = (col     < N_INT) ? bias[col]     : 0.0f;
        const float b1 = (col + 1 < N_INT) ? bias[col + 1] : 0.0f;
        #pragma unroll
        for (int mt = 0; mt < 4; ++mt) {
            const int row = row0 + wm + mt * 16 + g;
            float2 v0, v1;
            v0.x = 1.0f / (1.0f + __expf(-(acc[mt][nt][0] + b0)));
            v0.y = 1.0f / (1.0f + __expf(-(acc[mt][nt][1] + b1)));
            v1.x = 1.0f / (1.0f + __expf(-(acc[mt][nt][2] + b0)));
            v1.y = 1.0f / (1.0f + __expf(-(acc[mt][nt][3] + b1)));
            *(float2*)(g_P + (size_t)row * N_PAD + col)       = v0;
            *(float2*)(g_P + (size_t)(row + 8) * N_PAD + col) = v1;
        }
    }
}

// ===========================================================================
// Kernel 2 (fused): quad tree expansion -> fp16 prob_h -> HMMA GEMM2.
// (unchanged from R13 passing version)
// ===========================================================================
#define PH_LD   1032                       // halves per prob row
#define F_ROWS  16
#define FUSED_SMEM (F_ROWS * PH_LD * 2)    // 33024 B

__global__ __launch_bounds__(256)
void fused_tree_gemm2(float* __restrict__ out)
{
    extern __shared__ __half prob_h[];     // [16][PH_LD]
    const uint32_t pbase = smem_u32(prob_h);
    const int tid  = threadIdx.x;
    const int lane = tid & 31;
    const int wid  = tid >> 5;
    const int row0 = blockIdx.x * F_ROWS;

    // Phase B: 16 iters; item idx: row r = idx>>8, quad q = idx&255.
    #pragma unroll 2
    for (int i = 0; i < 16; ++i) {
        const int idx = i * 256 + tid;
        const int r   = idx >> 8;
        const int q   = idx & 255;
        const float* pr = g_P + (size_t)(row0 + r) * N_PAD;
        float w = 1.0f;
        #pragma unroll
        for (int lvl = 0; lvl < 8; ++lvl) {
            int node = (1 << lvl) - 1 + (q >> (8 - lvl));
            float pv = __ldg(pr + node);
            int bit  = (q >> (7 - lvl)) & 1;
            w *= bit ? (1.0f - pv) : pv;
        }
        const float p8   = __ldg(pr + 255 + q);
        const float p9a  = __ldg(pr + 511 + 2 * q);
        const float p9b  = __ldg(pr + 512 + 2 * q);
        const float w9a  = w * p8;
        const float w9b  = w * (1.0f - p8);
        __half2 h0 = __floats2half2_rn(w9a * p9a, w9a * (1.0f - p9a));
        __half2 h1 = __floats2half2_rn(w9b * p9b, w9b * (1.0f - p9b));
        uint2 u;
        u.x = *(uint32_t*)&h0;
        u.y = *(uint32_t*)&h1;
        *(uint2*)((char*)prob_h + (r * PH_LD + 4 * q) * 2) = u;
    }
    __syncthreads();

    // GEMM: warp wid -> n8 slice; M=16, K=1024 in 64 k16 steps.
    float acc[4] = {0.0f, 0.0f, 0.0f, 0.0f};
    const uint32_t aAddr = pbase + (uint32_t)((lane & 15) * (PH_LD * 2) + (lane >> 4) * 16);
    const uint2* bp = g_Lfrag + (size_t)(wid * 64) * 32 + lane;

    #pragma unroll 8
    for (int kt = 0; kt < 64; ++kt) {
        uint32_t a[4];
        LDSM_X4(a[0], a[1], a[2], a[3], aAddr + kt * 32);
        const uint2 b = __ldg(bp + kt * 32);
        mma_f16(acc, a, b.x, b.y);
    }

    // Epilogue: c frag -> out.
    {
        const int rr = row0 + (lane >> 2);
        const int cc = wid * 8 + (lane & 3) * 2;
        *(float2*)(out + (size_t)rr * LEAF_D + cc)       = make_float2(acc[0], acc[1]);
        *(float2*)(out + (size_t)(rr + 8) * LEAF_D + cc) = make_float2(acc[2], acc[3]);
    }
}

// ===========================================================================
extern "C" void kernel_launch(void* const* d_in, const int* in_sizes, int n_in,
                              void* d_out, int out_size)
{
    const float* x      = (const float*)d_in[0];   // [8192, 512]
    const float* W      = (const float*)d_in[1];   // [512, 1023]
    const float* bias   = (const float*)d_in[2];   // [1023]
    const float* leaves = (const float*)d_in[3];   // [1024, 64]
    float*       out    = (float*)d_out;           // [8192, 64]

    cudaFuncSetAttribute(gemm1_kernel,
                         cudaFuncAttributeMaxDynamicSharedMemorySize, G1_SMEM);
    cudaFuncSetAttribute(fused_tree_gemm2,
                         cudaFuncAttributeMaxDynamicSharedMemorySize, FUSED_SMEM);

    convert_x_kernel<<<B_ROWS * F_DIM / (256 * 8), 256>>>(x);
    convert_w_kernel<<<dim3(32, 16), dim3(32, 8)>>>(W);
    convert_leaves_kernel<<<64, 256>>>(leaves);
    gemm1_kernel<<<dim3(8, 64), 256, G1_SMEM>>>(bias);
    fused_tree_gemm2<<<512, 256, FUSED_SMEM>>>(out);
}

// round 15
// speedup vs baseline: 1.2869x; 1.2869x over previous
#include <cuda_runtime.h>
#include <cuda_fp16.h>
#include <cstdint>

#define B_ROWS   8192
#define F_DIM    512
#define N_INT    1023
#define N_PAD    1024
#define N_LEAVES 1024
#define LEAF_D   64
#define DEPTH    10

// Scratch (allocation-free device globals)
__device__ float  g_P[B_ROWS * N_PAD];      // sigmoid(xW+b), col 1023 junk
__device__ __half g_Xh[B_ROWS * F_DIM];     // x in fp16
__device__ __half g_Wh[N_PAD * F_DIM];      // W^T in fp16: [n][k], row 1023 zero
__device__ uint2  g_Lfrag[8 * 64 * 32];     // leaves in HMMA B-fragment order

__device__ __forceinline__ uint32_t smem_u32(const void* p) {
    uint32_t a;
    asm("{ .reg .u64 t; cvta.to.shared.u64 t, %1; cvt.u32.u64 %0, t; }" : "=r"(a) : "l"(p));
    return a;
}

// m16n8k16 fp16 MMA, f32 accum
__device__ __forceinline__ void mma_f16(float* d, const uint32_t* a,
                                        uint32_t b0, uint32_t b1) {
    asm volatile(
        "mma.sync.aligned.m16n8k16.row.col.f32.f16.f16.f32 "
        "{%0,%1,%2,%3}, {%4,%5,%6,%7}, {%8,%9}, {%0,%1,%2,%3};"
        : "+f"(d[0]), "+f"(d[1]), "+f"(d[2]), "+f"(d[3])
        : "r"(a[0]), "r"(a[1]), "r"(a[2]), "r"(a[3]), "r"(b0), "r"(b1));
}

#define LDSM_X4(r0, r1, r2, r3, addr)                                          \
    asm volatile("ldmatrix.sync.aligned.m8n8.x4.shared.b16 {%0,%1,%2,%3}, [%4];" \
                 : "=r"(r0), "=r"(r1), "=r"(r2), "=r"(r3) : "r"(addr))

#define CP_ASYNC16(saddr, gptr)                                                \
    asm volatile("cp.async.cg.shared.global [%0], [%1], 16;"                   \
                 :: "r"(saddr), "l"(gptr) : "memory")
#define CP_COMMIT()  asm volatile("cp.async.commit_group;" ::: "memory")
#define CP_WAIT1()   asm volatile("cp.async.wait_group 1;" ::: "memory")

// ===========================================================================
// Kernel 0: ALL converters in one launch (block-range dispatch).
// blocks [0, 2048): x -> g_Xh fp16 (8 elems/thread)
// blocks [2048, 2560): W -> g_Wh fp16 transposed (32x32 tiles)
// blocks [2560, 2624): leaves -> g_Lfrag HMMA B fragments
// ===========================================================================
__global__ __launch_bounds__(256)
void convert_all_kernel(const float* __restrict__ x,
                        const float* __restrict__ W,
                        const float* __restrict__ leaves)
{
    const int b   = blockIdx.x;
    const int tid = threadIdx.x;

    if (b < 2048) {
        // ---- x -> g_Xh ----
        const int i = (b * 256 + tid) * 8;
        float4 v0 = *(const float4*)(x + i);
        float4 v1 = *(const float4*)(x + i + 4);
        __half2 h0 = __floats2half2_rn(v0.x, v0.y);
        __half2 h1 = __floats2half2_rn(v0.z, v0.w);
        __half2 h2 = __floats2half2_rn(v1.x, v1.y);
        __half2 h3 = __floats2half2_rn(v1.z, v1.w);
        uint4 u;
        u.x = *(uint32_t*)&h0; u.y = *(uint32_t*)&h1;
        u.z = *(uint32_t*)&h2; u.w = *(uint32_t*)&h3;
        *(uint4*)(g_Xh + i) = u;
    } else if (b < 2560) {
        // ---- W -> g_Wh (transpose + fp16) ----
        __shared__ float t[32][33];
        const int idx = b - 2048;
        const int n0  = (idx & 31) * 32;
        const int k0  = (idx >> 5) * 32;
        const int tx  = tid & 31, ty = tid >> 5;    // 32 x 8
        #pragma unroll
        for (int i = 0; i < 4; ++i) {
            int k = k0 + ty + i * 8;
            int n = n0 + tx;
            t[ty + i * 8][tx] = (n < N_INT) ? W[(size_t)k * N_INT + n] : 0.0f;
        }
        __syncthreads();
        #pragma unroll
        for (int i = 0; i < 4; ++i) {
            int n = n0 + ty + i * 8;
            g_Wh[(size_t)n * F_DIM + k0 + tx] = __float2half_rn(t[tx][ty + i * 8]);
        }
    } else {
        // ---- leaves -> g_Lfrag ----
        const int gi   = (b - 2560) * 256 + tid;   // 0..16383
        const int wid  = gi >> 11;
        const int kt   = (gi >> 5) & 63;
        const int lane = gi & 31;
        const int n  = wid * 8 + (lane >> 2);
        const int k0 = kt * 16 + (lane & 3) * 2;
        __half2 b0 = __floats2half2_rn(leaves[(size_t)k0 * LEAF_D + n],
                                       leaves[(size_t)(k0 + 1) * LEAF_D + n]);
        __half2 b1 = __floats2half2_rn(leaves[(size_t)(k0 + 8) * LEAF_D + n],
                                       leaves[(size_t)(k0 + 9) * LEAF_D + n]);
        uint2 u;
        u.x = *(uint32_t*)&b0;
        u.y = *(uint32_t*)&b1;
        g_Lfrag[gi] = u;
    }
}

// ===========================================================================
// Kernel 1: P = sigmoid(x @ W + b). fp16 ldmatrix + mma, cp.async 3-stage.
// EXACT R13 config (measured 34.6us): 256 threads = 8 warps (2M x 4N),
// warp tile 64x32, CTA 128x128, BK=32, regs 126, 2 CTAs/SM.
// ===========================================================================
#define G1_STAGE  8192
#define G1_SMEM   (6 * G1_STAGE)

__global__ __launch_bounds__(256, 2)
void gemm1_kernel(const float* __restrict__ bias)
{
    extern __shared__ char smem[];
    const uint32_t sbase = smem_u32(smem);
    const int tid  = threadIdx.x;
    const int lane = tid & 31;
    const int wid  = tid >> 5;
    const int wm   = (wid & 1) * 64;
    const int wn   = (wid >> 1) * 32;
    const int row0 = blockIdx.y * 128;
    const int col0 = blockIdx.x * 128;

    float acc[4][4][4];
    #pragma unroll
    for (int mt = 0; mt < 4; ++mt)
        #pragma unroll
        for (int nt = 0; nt < 4; ++nt)
            #pragma unroll
            for (int i = 0; i < 4; ++i) acc[mt][nt][i] = 0.0f;

    const int lr0 = tid >> 2;
    const int lc  = tid & 3;
    const int lr1 = lr0 + 64;
    const uint32_t soff0 = (uint32_t)(lr0 * 64 + ((lc ^ ((lr0 >> 1) & 3)) << 4));
    const uint32_t soff1 = (uint32_t)(lr1 * 64 + ((lc ^ ((lr1 >> 1) & 3)) << 4));
    const __half* gA0 = g_Xh + (size_t)(row0 + lr0) * F_DIM + lc * 8;
    const __half* gA1 = g_Xh + (size_t)(row0 + lr1) * F_DIM + lc * 8;
    const __half* gB0 = g_Wh + (size_t)(col0 + lr0) * F_DIM + lc * 8;
    const __half* gB1 = g_Wh + (size_t)(col0 + lr1) * F_DIM + lc * 8;

    #define LOAD_STAGE(st, bk)                                                 \
    do {                                                                       \
        uint32_t a_ = sbase + (st) * G1_STAGE;                                 \
        uint32_t b_ = sbase + 3 * G1_STAGE + (st) * G1_STAGE;                  \
        CP_ASYNC16(a_ + soff0, gA0 + (bk));                                    \
        CP_ASYNC16(a_ + soff1, gA1 + (bk));                                    \
        CP_ASYNC16(b_ + soff0, gB0 + (bk));                                    \
        CP_ASYNC16(b_ + soff1, gB1 + (bk));                                    \
    } while (0)

    const int arow = wm + (lane & 15);
    const int ax   = (arow >> 1) & 3;
    const int ahi  = lane >> 4;
    const uint32_t aAddr0 = (uint32_t)(arow * 64 + (((0 + ahi) ^ ax) << 4));
    const uint32_t aAddr1 = (uint32_t)(arow * 64 + (((2 + ahi) ^ ax) << 4));

    const int brow = wn + (lane & 7) + ((lane >> 4) << 3);
    const int bx   = (brow >> 1) & 3;
    const int bhi  = (lane >> 3) & 1;
    const uint32_t bAddr0 = (uint32_t)(brow * 64 + (((0 + bhi) ^ bx) << 4));
    const uint32_t bAddr1 = (uint32_t)(brow * 64 + (((2 + bhi) ^ bx) << 4));

    #define COMPUTE(st)                                                        \
    do {                                                                       \
        const uint32_t ab = sbase + (st) * G1_STAGE;                           \
        const uint32_t bb = sbase + 3 * G1_STAGE + (st) * G1_STAGE;            \
        _Pragma("unroll")                                                      \
        for (int s = 0; s < 2; ++s) {                                          \
            const uint32_t aA = (s == 0) ? aAddr0 : aAddr1;                    \
            const uint32_t bA = (s == 0) ? bAddr0 : bAddr1;                    \
            uint32_t a[4][4], b[2][4];                                         \
            _Pragma("unroll")                                                  \
            for (int mt = 0; mt < 4; ++mt)                                     \
                LDSM_X4(a[mt][0], a[mt][1], a[mt][2], a[mt][3],                \
                        ab + aA + mt * 1024);                                  \
            _Pragma("unroll")                                                  \
            for (int n2 = 0; n2 < 2; ++n2)                                     \
                LDSM_X4(b[n2][0], b[n2][1], b[n2][2], b[n2][3],                \
                        bb + bA + n2 * 1024);                                  \
            _Pragma("unroll")                                                  \
            for (int mt = 0; mt < 4; ++mt)                                     \
                _Pragma("unroll")                                              \
                for (int nt = 0; nt < 4; ++nt)                                 \
                    mma_f16(acc[mt][nt], a[mt],                                \
                            b[nt >> 1][(nt & 1) * 2],                          \
                            b[nt >> 1][(nt & 1) * 2 + 1]);                     \
        }                                                                      \
    } while (0)

    LOAD_STAGE(0, 0);  CP_COMMIT();
    LOAD_STAGE(1, 32); CP_COMMIT();

    for (int it = 0; it < 16; ++it) {
        CP_WAIT1();
        __syncthreads();
        if (it < 14) LOAD_STAGE((it + 2) % 3, (it + 2) * 32);
        CP_COMMIT();
        COMPUTE(it % 3);
    }
    #undef COMPUTE
    #undef LOAD_STAGE

    const int g = lane >> 2, t = lane & 3;
    #pragma unroll
    for (int nt = 0; nt < 4; ++nt) {
        const int col = col0 + wn + nt * 8 + 2 * t;
        const float b0 = (col     < N_INT) ? bias[col]     : 0.0f;
        const float b1 = (col + 1 < N_INT) ? bias[col + 1] : 0.0f;
        #pragma unroll
        for (int mt = 0; mt < 4; ++mt) {
            const int row = row0 + wm + mt * 16 + g;
            float2 v0, v1;
            v0.x = 1.0f / (1.0f + __expf(-(acc[mt][nt][0] + b0)));
            v0.y = 1.0f / (1.0f + __expf(-(acc[mt][nt][1] + b1)));
            v1.x = 1.0f / (1.0f + __expf(-(acc[mt][nt][2] + b0)));
            v1.y = 1.0f / (1.0f + __expf(-(acc[mt][nt][3] + b1)));
            *(float2*)(g_P + (size_t)row * N_PAD + col)       = v0;
            *(float2*)(g_P + (size_t)(row + 8) * N_PAD + col) = v1;
        }
    }
}

// ===========================================================================
// Kernel 2 (fused): OCT tree expansion -> fp16 prob_h -> HMMA GEMM2.
// 16 rows per CTA, 256 threads = 8 warps, grid = 512.
// Phase B (oct): thread handles leaves 8o..8o+7 — levels 0..6, node7,
// and both node8s shared: 14 LDG / 8 leaves (was 22). Multiply order
// identical to quad version -> bitwise-identical output. One STS.128.
// GEMM: per warp n8 slice; k16 step = 1 LDSM.x4 + 1 coalesced LDG.64 + HMMA.
// ===========================================================================
#define PH_LD   1032                       // halves per prob row
#define F_ROWS  16
#define FUSED_SMEM (F_ROWS * PH_LD * 2)    // 33024 B

__global__ __launch_bounds__(256)
void fused_tree_gemm2(float* __restrict__ out)
{
    extern __shared__ __half prob_h[];     // [16][PH_LD]
    const uint32_t pbase = smem_u32(prob_h);
    const int tid  = threadIdx.x;
    const int lane = tid & 31;
    const int wid  = tid >> 5;
    const int row0 = blockIdx.x * F_ROWS;

    // Phase B: 8 iters; item idx: row r = idx>>7, oct o = idx&127.
    #pragma unroll 2
    for (int i = 0; i < 8; ++i) {
        const int idx = i * 256 + tid;
        const int r   = idx >> 7;
        const int o   = idx & 127;
        const float* pr = g_P + (size_t)(row0 + r) * N_PAD;
        float w = 1.0f;
        #pragma unroll
        for (int lvl = 0; lvl < 7; ++lvl) {
            int node = (1 << lvl) - 1 + (o >> (7 - lvl));
            float pv = __ldg(pr + node);
            int bit  = (o >> (6 - lvl)) & 1;
            w *= bit ? (1.0f - pv) : pv;
        }
        const float p7  = __ldg(pr + 127 + o);
        const float p8a = __ldg(pr + 255 + 2 * o);
        const float p8b = __ldg(pr + 256 + 2 * o);
        const float p9a = __ldg(pr + 511 + 4 * o);
        const float p9b = __ldg(pr + 512 + 4 * o);
        const float p9c = __ldg(pr + 513 + 4 * o);
        const float p9d = __ldg(pr + 514 + 4 * o);
        const float wa  = w  * p7;
        const float wb  = w  * (1.0f - p7);
        const float waa = wa * p8a;
        const float wab = wa * (1.0f - p8a);
        const float wba = wb * p8b;
        const float wbb = wb * (1.0f - p8b);
        __half2 h0 = __floats2half2_rn(waa * p9a, waa * (1.0f - p9a));
        __half2 h1 = __floats2half2_rn(wab * p9b, wab * (1.0f - p9b));
        __half2 h2 = __floats2half2_rn(wba * p9c, wba * (1.0f - p9c));
        __half2 h3 = __floats2half2_rn(wbb * p9d, wbb * (1.0f - p9d));
        uint4 u;
        u.x = *(uint32_t*)&h0;
        u.y = *(uint32_t*)&h1;
        u.z = *(uint32_t*)&h2;
        u.w = *(uint32_t*)&h3;
        *(uint4*)((char*)prob_h + (r * PH_LD + 8 * o) * 2) = u;
    }
    __syncthreads();

    // GEMM: warp wid -> n8 slice; M=16, K=1024 in 64 k16 steps.
    float acc[4] = {0.0f, 0.0f, 0.0f, 0.0f};
    const uint32_t aAddr = pbase + (uint32_t)((lane & 15) * (PH_LD * 2) + (lane >> 4) * 16);
    const uint2* bp = g_Lfrag + (size_t)(wid * 64) * 32 + lane;

    #pragma unroll 8
    for (int kt = 0; kt < 64; ++kt) {
        uint32_t a[4];
        LDSM_X4(a[0], a[1], a[2], a[3], aAddr + kt * 32);
        const uint2 b = __ldg(bp + kt * 32);
        mma_f16(acc, a, b.x, b.y);
    }

    // Epilogue: c frag -> out.
    {
        const int rr = row0 + (lane >> 2);
        const int cc = wid * 8 + (lane & 3) * 2;
        *(float2*)(out + (size_t)rr * LEAF_D + cc)       = make_float2(acc[0], acc[1]);
        *(float2*)(out + (size_t)(rr + 8) * LEAF_D + cc) = make_float2(acc[2], acc[3]);
    }
}

// ===========================================================================
extern "C" void kernel_launch(void* const* d_in, const int* in_sizes, int n_in,
                              void* d_out, int out_size)
{
    const float* x      = (const float*)d_in[0];   // [8192, 512]
    const float* W      = (const float*)d_in[1];   // [512, 1023]
    const float* bias   = (const float*)d_in[2];   // [1023]
    const float* leaves = (const float*)d_in[3];   // [1024, 64]
    float*       out    = (float*)d_out;           // [8192, 64]

    cudaFuncSetAttribute(gemm1_kernel,
                         cudaFuncAttributeMaxDynamicSharedMemorySize, G1_SMEM);
    cudaFuncSetAttribute(fused_tree_gemm2,
                         cudaFuncAttributeMaxDynamicSharedMemorySize, FUSED_SMEM);

    convert_all_kernel<<<2624, 256>>>(x, W, leaves);
    gemm1_kernel<<<dim3(8, 64), 256, G1_SMEM>>>(bias);
    fused_tree_gemm2<<<512, 256, FUSED_SMEM>>>(out);
}